// round 1
// baseline (speedup 1.0000x reference)
#include <cuda_runtime.h>
#include <math.h>
#include <stdint.h>

// Problem constants
#define B_    4
#define N_    1024
#define DIM_  768
#define H_    12
#define KV_   4
#define D_    64
#define SIDE_ 32
#define WIN_  8
#define REP_  (H_ / KV_)       // 3
#define M_ROWS (B_ * N_)       // 4096

// ---------------------------------------------------------------------------
// Scratch (static __device__ arrays; no allocation allowed)
// ---------------------------------------------------------------------------
__device__ float g_q  [M_ROWS * 2 * DIM_];   // 4096 x 1536  (s,h,d packed)
__device__ float g_k  [M_ROWS * 512];        // 4096 x 512   (s,kh,d packed)
__device__ float g_v1 [M_ROWS * 256];        // 4096 x 256
__device__ float g_v2 [M_ROWS * 256];        // 4096 x 256
__device__ float g_ctx[M_ROWS * DIM_];       // 4096 x 768   (h,d packed)

// ---------------------------------------------------------------------------
// GEMM: C[M,N] = A[M,K] * W[N,K]^T (+bias). M%64==0, N%64==0, K%16==0.
// 64x64 block tile, 16 K-tile, 256 threads, 4x4 per-thread microtile.
// ---------------------------------------------------------------------------
#define BM 64
#define BN 64
#define BK 16

__global__ __launch_bounds__(256)
void gemm_nt(const float* __restrict__ A, const float* __restrict__ W,
             const float* __restrict__ bias, float* __restrict__ C,
             int M, int N, int K)
{
    __shared__ float As[BK][BM + 1];
    __shared__ float Ws[BK][BN + 1];

    const int tid = threadIdx.x;
    const int tx  = tid & 15;    // 0..15 -> N direction
    const int ty  = tid >> 4;    // 0..15 -> M direction
    const int m0  = blockIdx.y * BM;
    const int n0  = blockIdx.x * BN;

    float acc[4][4];
#pragma unroll
    for (int i = 0; i < 4; i++)
#pragma unroll
        for (int j = 0; j < 4; j++) acc[i][j] = 0.f;

    for (int k0 = 0; k0 < K; k0 += BK) {
#pragma unroll
        for (int i = tid; i < BM * BK; i += 256) {
            int r = i >> 4, c = i & 15;
            As[c][r] = A[(size_t)(m0 + r) * K + k0 + c];
        }
#pragma unroll
        for (int i = tid; i < BN * BK; i += 256) {
            int r = i >> 4, c = i & 15;
            Ws[c][r] = W[(size_t)(n0 + r) * K + k0 + c];
        }
        __syncthreads();

#pragma unroll
        for (int kk = 0; kk < BK; kk++) {
            float a[4], w[4];
#pragma unroll
            for (int i = 0; i < 4; i++) a[i] = As[kk][ty * 4 + i];
#pragma unroll
            for (int j = 0; j < 4; j++) w[j] = Ws[kk][tx * 4 + j];
#pragma unroll
            for (int i = 0; i < 4; i++)
#pragma unroll
                for (int j = 0; j < 4; j++)
                    acc[i][j] += a[i] * w[j];
        }
        __syncthreads();
    }

#pragma unroll
    for (int i = 0; i < 4; i++) {
        int m = m0 + ty * 4 + i;
#pragma unroll
        for (int j = 0; j < 4; j++) {
            int n = n0 + tx * 4 + j;
            float v = acc[i][j];
            if (bias) v += bias[n];
            C[(size_t)m * N + n] = v;
        }
    }
}

// ---------------------------------------------------------------------------
// 2D RoPE + qk-norm. One warp per 64-vector. buf has `vpr` vectors per row
// of `stride` floats; total_rows = B*N; n = row % 1024 gives grid position.
// ---------------------------------------------------------------------------
__global__ __launch_bounds__(256)
void rope_norm(float* __restrict__ buf, int vpr, int stride, int total_vec)
{
    const int gw   = (blockIdx.x * blockDim.x + threadIdx.x) >> 5;
    const int lane = threadIdx.x & 31;
    if (gw >= total_vec) return;

    const int row = gw / vpr;
    const int vec = gw - row * vpr;
    const int n   = row & (N_ - 1);
    const float ph = (float)(n >> 5);
    const float pw = (float)(n & 31);

    float* p = buf + (size_t)row * stride + vec * 64;
    float x0 = p[lane];
    float x1 = p[lane + 32];

    // theta: dims [0,32) use pos_h with freq idx=lane; dims [32,64) use pos_w, same idx
    float inv = powf(10000.f, -(float)lane / 32.f);
    float t0 = ph * inv, t1 = pw * inv;
    float c0, s0, c1, s1;
    sincosf(t0, &s0, &c0);
    sincosf(t1, &s1, &c1);

    // rotate_half: pairs (2i,2i+1): out[2i] uses -x[2i+1]; out[2i+1] uses +x[2i]
    float px0 = __shfl_xor_sync(0xffffffffu, x0, 1);
    float px1 = __shfl_xor_sync(0xffffffffu, x1, 1);
    float r0 = (lane & 1) ? px0 : -px0;
    float r1 = (lane & 1) ? px1 : -px1;

    float o0 = x0 * c0 + r0 * s0;
    float o1 = x1 * c1 + r1 * s1;

    float ss = o0 * o0 + o1 * o1;
#pragma unroll
    for (int o = 16; o; o >>= 1) ss += __shfl_xor_sync(0xffffffffu, ss, o);
    float sc = 1.f / (sqrtf(ss) + 1e-6f);

    p[lane]      = o0 * sc;
    p[lane + 32] = o1 * sc;
}

// ---------------------------------------------------------------------------
// Windowed differential attention. One warp per (b,h,query). 4 warps/block.
// Two-pass softmax with scores in shared memory. Writes g_ctx[(b,n),(h,d)].
// ---------------------------------------------------------------------------
#define AW 4   // warps per block

__global__ __launch_bounds__(AW * 32)
void attn_kernel(const float* __restrict__ lambda_p)
{
    __shared__ float sq1[AW][64];
    __shared__ float sq2[AW][64];
    __shared__ float sp1[AW][292];
    __shared__ float sp2[AW][292];

    const int w    = threadIdx.x >> 5;
    const int lane = threadIdx.x & 31;
    const int gq   = blockIdx.x * AW + w;     // 0 .. B*H*N-1
    const int b    = gq / (H_ * N_);
    const int h    = (gq / N_) % H_;
    const int n    = gq & (N_ - 1);
    const int kh   = h / REP_;

    const int ph = n >> 5, pw = n & 31;
    const int r0 = max(ph - WIN_, 0), r1 = min(ph + WIN_, SIDE_ - 1);
    const int c0 = max(pw - WIN_, 0), c1 = min(pw + WIN_, SIDE_ - 1);
    const int nc = c1 - c0 + 1;
    const int cnt = (r1 - r0 + 1) * nc;

    // load q into shared (2 sides of 64)
    const size_t qbase = (size_t)(b * N_ + n) * (2 * DIM_) + h * 64;
    sq1[w][lane]      = g_q[qbase + lane];
    sq1[w][lane + 32] = g_q[qbase + lane + 32];
    sq2[w][lane]      = g_q[qbase + DIM_ + lane];
    sq2[w][lane + 32] = g_q[qbase + DIM_ + lane + 32];
    __syncwarp();

    // pass 1: per-lane keys, full 64-dot per key, both sides
    float s1loc[10], s2loc[10];
    int nloc = 0;
    float m1 = -1e30f, m2 = -1e30f;
    for (int t = lane; t < cnt; t += 32) {
        int r = r0 + t / nc;
        int c = c0 + t - (t / nc) * nc;
        int m = r * 32 + c;
        const float4* k1p = reinterpret_cast<const float4*>(
            g_k + (size_t)(b * N_ + m) * 512 + kh * 64);
        const float4* k2p = k1p + 64;  // +256 floats
        float s1 = 0.f, s2 = 0.f;
        const float* q1 = sq1[w];
        const float* q2 = sq2[w];
#pragma unroll
        for (int i = 0; i < 16; i++) {
            float4 k1v = k1p[i];
            float4 k2v = k2p[i];
            s1 += q1[4*i+0]*k1v.x + q1[4*i+1]*k1v.y + q1[4*i+2]*k1v.z + q1[4*i+3]*k1v.w;
            s2 += q2[4*i+0]*k2v.x + q2[4*i+1]*k2v.y + q2[4*i+2]*k2v.z + q2[4*i+3]*k2v.w;
        }
        s1 *= 0.125f; s2 *= 0.125f;
        s1loc[nloc] = s1; s2loc[nloc] = s2; nloc++;
        m1 = fmaxf(m1, s1); m2 = fmaxf(m2, s2);
    }
#pragma unroll
    for (int o = 16; o; o >>= 1) {
        m1 = fmaxf(m1, __shfl_xor_sync(0xffffffffu, m1, o));
        m2 = fmaxf(m2, __shfl_xor_sync(0xffffffffu, m2, o));
    }

    // pass 2: exp + write to shared, accumulate sums
    float sum1 = 0.f, sum2 = 0.f;
    {
        int i = 0;
        for (int t = lane; t < cnt; t += 32, i++) {
            float e1 = expf(s1loc[i] - m1);
            float e2 = expf(s2loc[i] - m2);
            sp1[w][t] = e1; sp2[w][t] = e2;
            sum1 += e1; sum2 += e2;
        }
    }
#pragma unroll
    for (int o = 16; o; o >>= 1) {
        sum1 += __shfl_xor_sync(0xffffffffu, sum1, o);
        sum2 += __shfl_xor_sync(0xffffffffu, sum2, o);
    }
    __syncwarp();

    // pass 3: dim-parallel weighted sum of V (coalesced loads)
    float a1a = 0.f, a1b = 0.f, a2a = 0.f, a2b = 0.f;
    int t = 0;
    for (int r = r0; r <= r1; r++) {
        size_t rowbase = (size_t)(b * N_ + r * 32 + c0);
        for (int c = 0; c < nc; c++, t++) {
            const float* v1p = g_v1 + (rowbase + c) * 256 + kh * 64;
            const float* v2p = g_v2 + (rowbase + c) * 256 + kh * 64;
            float p1 = sp1[w][t], p2 = sp2[w][t];
            a1a += p1 * v1p[lane];
            a1b += p1 * v1p[lane + 32];
            a2a += p2 * v2p[lane];
            a2b += p2 * v2p[lane + 32];
        }
    }
    float inv1 = 1.f / sum1, inv2 = 1.f / sum2;
    float lam = log1pf(expf(lambda_p[h]));

    float oa = a1a * inv1 - lam * (a2a * inv2);
    float ob = a1b * inv1 - lam * (a2b * inv2);

    float* dst = g_ctx + (size_t)(b * N_ + n) * DIM_ + h * 64;
    dst[lane]      = oa;
    dst[lane + 32] = ob;
}

// ---------------------------------------------------------------------------
// Launch
// ---------------------------------------------------------------------------
extern "C" void kernel_launch(void* const* d_in, const int* in_sizes, int n_in,
                              void* d_out, int out_size)
{
    const float* x      = (const float*)d_in[0];
    const float* Wq     = (const float*)d_in[1];
    const float* Wk     = (const float*)d_in[2];
    const float* Wv1    = (const float*)d_in[3];
    const float* Wv2    = (const float*)d_in[4];
    const float* lam_p  = (const float*)d_in[5];
    const float* Wo     = (const float*)d_in[6];
    const float* bo     = (const float*)d_in[7];
    float* out = (float*)d_out;

    float *qb, *kb, *v1b, *v2b, *ctx;
    cudaGetSymbolAddress((void**)&qb,  g_q);
    cudaGetSymbolAddress((void**)&kb,  g_k);
    cudaGetSymbolAddress((void**)&v1b, g_v1);
    cudaGetSymbolAddress((void**)&v2b, g_v2);
    cudaGetSymbolAddress((void**)&ctx, g_ctx);

    // projections
    {
        dim3 t(256);
        gemm_nt<<<dim3((2 * DIM_) / BN, M_ROWS / BM), t>>>(x, Wq, nullptr, qb,  M_ROWS, 2 * DIM_, DIM_);
        gemm_nt<<<dim3(512 / BN,        M_ROWS / BM), t>>>(x, Wk, nullptr, kb,  M_ROWS, 512, DIM_);
        gemm_nt<<<dim3(256 / BN,        M_ROWS / BM), t>>>(x, Wv1, nullptr, v1b, M_ROWS, 256, DIM_);
        gemm_nt<<<dim3(256 / BN,        M_ROWS / BM), t>>>(x, Wv2, nullptr, v2b, M_ROWS, 256, DIM_);
    }

    // RoPE + qk-norm (q: 24 vectors/row, k: 8 vectors/row)
    {
        int qvec = M_ROWS * 24;
        int kvec = M_ROWS * 8;
        rope_norm<<<(qvec * 32 + 255) / 256, 256>>>(qb, 24, 2 * DIM_, qvec);
        rope_norm<<<(kvec * 32 + 255) / 256, 256>>>(kb, 8, 512, kvec);
    }

    // windowed differential attention
    {
        int total_q = B_ * H_ * N_;
        attn_kernel<<<total_q / AW, AW * 32>>>(lam_p);
    }

    // output projection + bias
    gemm_nt<<<dim3(DIM_ / BN, M_ROWS / BM), 256>>>(ctx, Wo, bo, out, M_ROWS, DIM_, DIM_);
}

// round 2
// speedup vs baseline: 1.3949x; 1.3949x over previous
#include <cuda_runtime.h>
#include <math.h>
#include <stdint.h>

// Problem constants
#define B_    4
#define N_    1024
#define DIM_  768
#define H_    12
#define KV_   4
#define D_    64
#define SIDE_ 32
#define WIN_  8
#define REP_  (H_ / KV_)       // 3
#define M_ROWS (B_ * N_)       // 4096

// ---------------------------------------------------------------------------
// Scratch
// ---------------------------------------------------------------------------
__device__ float g_q  [M_ROWS * 2 * DIM_];   // 4096 x 1536
__device__ float g_k  [M_ROWS * 512];        // 4096 x 512
__device__ float g_v1 [M_ROWS * 256];
__device__ float g_v2 [M_ROWS * 256];
__device__ float g_ctx[M_ROWS * DIM_];

// ---------------------------------------------------------------------------
// TF32 tensor-core GEMM: C[M,N] = A[M,K] * W[N,K]^T (+bias)
// 128x64 block tile, K-tile 32, 256 threads (8 warps, 4x2), 32x32 warp tile.
// mma.sync.aligned.m16n8k8.row.col.f32.tf32.tf32.f32
// ---------------------------------------------------------------------------
#define TBM 128
#define TBN 64
#define TBK 32

__device__ __forceinline__ float to_tf32(float x) {
    asm("cvt.rna.tf32.f32 %0, %0;" : "+f"(x));
    return x;
}

__global__ __launch_bounds__(256)
void gemm_tf32(const float* __restrict__ A, const float* __restrict__ W,
               const float* __restrict__ bias, float* __restrict__ C,
               int M, int N, int K)
{
    // As stored k-major: As[k][m], pad 4 -> fragment LDS bank = (4*tig + gid): conflict-free
    __shared__ float As[TBK][TBM + 4];
    // Ws stored n-major: Ws[n][k], pad 4 -> fragment LDS bank = (4*gid + tig): conflict-free
    __shared__ float Ws[TBN][TBK + 4];

    const int tid  = threadIdx.x;
    const int lane = tid & 31;
    const int warp = tid >> 5;
    const int wm   = warp >> 1;          // 0..3
    const int wn   = warp & 1;           // 0..1
    const int gid  = lane >> 2;          // 0..7
    const int tig  = lane & 3;           // 0..3

    const int m0 = blockIdx.y * TBM;
    const int n0 = blockIdx.x * TBN;

    const int arow = tid >> 3;           // 0..31
    const int acol = (tid & 7) * 4;      // 0,4,..28

    float acc[2][4][4];
#pragma unroll
    for (int i = 0; i < 2; i++)
#pragma unroll
        for (int j = 0; j < 4; j++)
#pragma unroll
            for (int l = 0; l < 4; l++) acc[i][j][l] = 0.f;

    const int nkt = K / TBK;

    float4 pA[4], pW[2];

    // load tile 0 into prefetch regs
#pragma unroll
    for (int i = 0; i < 4; i++)
        pA[i] = *reinterpret_cast<const float4*>(A + (size_t)(m0 + arow + 32 * i) * K + acol);
#pragma unroll
    for (int i = 0; i < 2; i++)
        pW[i] = *reinterpret_cast<const float4*>(W + (size_t)(n0 + arow + 32 * i) * K + acol);

    for (int kt = 0; kt < nkt; kt++) {
        // store prefetched tile to smem (tf32-rounded)
#pragma unroll
        for (int i = 0; i < 4; i++) {
            int r = arow + 32 * i;
            As[acol + 0][r] = to_tf32(pA[i].x);
            As[acol + 1][r] = to_tf32(pA[i].y);
            As[acol + 2][r] = to_tf32(pA[i].z);
            As[acol + 3][r] = to_tf32(pA[i].w);
        }
#pragma unroll
        for (int i = 0; i < 2; i++) {
            float4 v = pW[i];
            v.x = to_tf32(v.x); v.y = to_tf32(v.y);
            v.z = to_tf32(v.z); v.w = to_tf32(v.w);
            *reinterpret_cast<float4*>(&Ws[arow + 32 * i][acol]) = v;
        }
        __syncthreads();

        // prefetch next tile
        if (kt + 1 < nkt) {
            int kb = (kt + 1) * TBK;
#pragma unroll
            for (int i = 0; i < 4; i++)
                pA[i] = *reinterpret_cast<const float4*>(A + (size_t)(m0 + arow + 32 * i) * K + kb + acol);
#pragma unroll
            for (int i = 0; i < 2; i++)
                pW[i] = *reinterpret_cast<const float4*>(W + (size_t)(n0 + arow + 32 * i) * K + kb + acol);
        }

        // compute 4 k-steps of 8
#pragma unroll
        for (int ks = 0; ks < 4; ks++) {
            const int kk = ks * 8;
            uint32_t a[2][4], b[4][2];
#pragma unroll
            for (int mt = 0; mt < 2; mt++) {
                int m = wm * 32 + mt * 16 + gid;
                a[mt][0] = __float_as_uint(As[kk + tig][m]);
                a[mt][1] = __float_as_uint(As[kk + tig][m + 8]);
                a[mt][2] = __float_as_uint(As[kk + tig + 4][m]);
                a[mt][3] = __float_as_uint(As[kk + tig + 4][m + 8]);
            }
#pragma unroll
            for (int nt = 0; nt < 4; nt++) {
                int n = wn * 32 + nt * 8 + gid;
                b[nt][0] = __float_as_uint(Ws[n][kk + tig]);
                b[nt][1] = __float_as_uint(Ws[n][kk + tig + 4]);
            }
#pragma unroll
            for (int mt = 0; mt < 2; mt++)
#pragma unroll
                for (int nt = 0; nt < 4; nt++) {
                    asm volatile(
                        "mma.sync.aligned.m16n8k8.row.col.f32.tf32.tf32.f32 "
                        "{%0,%1,%2,%3}, {%4,%5,%6,%7}, {%8,%9}, {%0,%1,%2,%3};\n"
                        : "+f"(acc[mt][nt][0]), "+f"(acc[mt][nt][1]),
                          "+f"(acc[mt][nt][2]), "+f"(acc[mt][nt][3])
                        : "r"(a[mt][0]), "r"(a[mt][1]), "r"(a[mt][2]), "r"(a[mt][3]),
                          "r"(b[nt][0]), "r"(b[nt][1]));
                }
        }
        __syncthreads();
    }

    // epilogue: c0,c1 at (gid, 2tig..2tig+1); c2,c3 at (gid+8, ...)
#pragma unroll
    for (int mt = 0; mt < 2; mt++) {
        int m = m0 + wm * 32 + mt * 16 + gid;
#pragma unroll
        for (int nt = 0; nt < 4; nt++) {
            int n = n0 + wn * 32 + nt * 8 + 2 * tig;
            float b0 = bias ? bias[n] : 0.f;
            float b1 = bias ? bias[n + 1] : 0.f;
            float2 r0 = make_float2(acc[mt][nt][0] + b0, acc[mt][nt][1] + b1);
            float2 r1 = make_float2(acc[mt][nt][2] + b0, acc[mt][nt][3] + b1);
            *reinterpret_cast<float2*>(C + (size_t)m * N + n) = r0;
            *reinterpret_cast<float2*>(C + (size_t)(m + 8) * N + n) = r1;
        }
    }
}

// ---------------------------------------------------------------------------
// 2D RoPE + qk-norm (one warp per 64-vector).
// ---------------------------------------------------------------------------
__global__ __launch_bounds__(256)
void rope_norm(float* __restrict__ buf, int vpr, int stride, int total_vec)
{
    const int gw   = (blockIdx.x * blockDim.x + threadIdx.x) >> 5;
    const int lane = threadIdx.x & 31;
    if (gw >= total_vec) return;

    const int row = gw / vpr;
    const int vec = gw - row * vpr;
    const int n   = row & (N_ - 1);
    const float ph = (float)(n >> 5);
    const float pw = (float)(n & 31);

    float* p = buf + (size_t)row * stride + vec * 64;
    float x0 = p[lane];
    float x1 = p[lane + 32];

    // inv_freq = 10000^(-lane/32) = exp2(-lane * log2(10000)/32)
    float inv = exp2f((float)lane * -0.4152410118609203f);
    float t0 = ph * inv, t1 = pw * inv;
    float c0, s0, c1, s1;
    sincosf(t0, &s0, &c0);
    sincosf(t1, &s1, &c1);

    float px0 = __shfl_xor_sync(0xffffffffu, x0, 1);
    float px1 = __shfl_xor_sync(0xffffffffu, x1, 1);
    float r0 = (lane & 1) ? px0 : -px0;
    float r1 = (lane & 1) ? px1 : -px1;

    float o0 = x0 * c0 + r0 * s0;
    float o1 = x1 * c1 + r1 * s1;

    float ss = o0 * o0 + o1 * o1;
#pragma unroll
    for (int o = 16; o; o >>= 1) ss += __shfl_xor_sync(0xffffffffu, ss, o);
    float sc = 1.f / (sqrtf(ss) + 1e-6f);

    p[lane]      = o0 * sc;
    p[lane + 32] = o1 * sc;
}

// ---------------------------------------------------------------------------
// Windowed differential attention (unchanged from round 1).
// ---------------------------------------------------------------------------
#define AW 4

__global__ __launch_bounds__(AW * 32)
void attn_kernel(const float* __restrict__ lambda_p)
{
    __shared__ float sq1[AW][64];
    __shared__ float sq2[AW][64];
    __shared__ float sp1[AW][292];
    __shared__ float sp2[AW][292];

    const int w    = threadIdx.x >> 5;
    const int lane = threadIdx.x & 31;
    const int gq   = blockIdx.x * AW + w;
    const int b    = gq / (H_ * N_);
    const int h    = (gq / N_) % H_;
    const int n    = gq & (N_ - 1);
    const int kh   = h / REP_;

    const int ph = n >> 5, pw = n & 31;
    const int r0 = max(ph - WIN_, 0), r1 = min(ph + WIN_, SIDE_ - 1);
    const int c0 = max(pw - WIN_, 0), c1 = min(pw + WIN_, SIDE_ - 1);
    const int nc = c1 - c0 + 1;
    const int cnt = (r1 - r0 + 1) * nc;

    const size_t qbase = (size_t)(b * N_ + n) * (2 * DIM_) + h * 64;
    sq1[w][lane]      = g_q[qbase + lane];
    sq1[w][lane + 32] = g_q[qbase + lane + 32];
    sq2[w][lane]      = g_q[qbase + DIM_ + lane];
    sq2[w][lane + 32] = g_q[qbase + DIM_ + lane + 32];
    __syncwarp();

    float s1loc[10], s2loc[10];
    int nloc = 0;
    float m1 = -1e30f, m2 = -1e30f;
    for (int t = lane; t < cnt; t += 32) {
        int r = r0 + t / nc;
        int c = c0 + t - (t / nc) * nc;
        int m = r * 32 + c;
        const float4* k1p = reinterpret_cast<const float4*>(
            g_k + (size_t)(b * N_ + m) * 512 + kh * 64);
        const float4* k2p = k1p + 64;
        float s1 = 0.f, s2 = 0.f;
        const float* q1 = sq1[w];
        const float* q2 = sq2[w];
#pragma unroll
        for (int i = 0; i < 16; i++) {
            float4 k1v = k1p[i];
            float4 k2v = k2p[i];
            s1 += q1[4*i+0]*k1v.x + q1[4*i+1]*k1v.y + q1[4*i+2]*k1v.z + q1[4*i+3]*k1v.w;
            s2 += q2[4*i+0]*k2v.x + q2[4*i+1]*k2v.y + q2[4*i+2]*k2v.z + q2[4*i+3]*k2v.w;
        }
        s1 *= 0.125f; s2 *= 0.125f;
        s1loc[nloc] = s1; s2loc[nloc] = s2; nloc++;
        m1 = fmaxf(m1, s1); m2 = fmaxf(m2, s2);
    }
#pragma unroll
    for (int o = 16; o; o >>= 1) {
        m1 = fmaxf(m1, __shfl_xor_sync(0xffffffffu, m1, o));
        m2 = fmaxf(m2, __shfl_xor_sync(0xffffffffu, m2, o));
    }

    float sum1 = 0.f, sum2 = 0.f;
    {
        int i = 0;
        for (int t = lane; t < cnt; t += 32, i++) {
            float e1 = expf(s1loc[i] - m1);
            float e2 = expf(s2loc[i] - m2);
            sp1[w][t] = e1; sp2[w][t] = e2;
            sum1 += e1; sum2 += e2;
        }
    }
#pragma unroll
    for (int o = 16; o; o >>= 1) {
        sum1 += __shfl_xor_sync(0xffffffffu, sum1, o);
        sum2 += __shfl_xor_sync(0xffffffffu, sum2, o);
    }
    __syncwarp();

    float a1a = 0.f, a1b = 0.f, a2a = 0.f, a2b = 0.f;
    int t = 0;
    for (int r = r0; r <= r1; r++) {
        size_t rowbase = (size_t)(b * N_ + r * 32 + c0);
        for (int c = 0; c < nc; c++, t++) {
            const float* v1p = g_v1 + (rowbase + c) * 256 + kh * 64;
            const float* v2p = g_v2 + (rowbase + c) * 256 + kh * 64;
            float p1 = sp1[w][t], p2 = sp2[w][t];
            a1a += p1 * v1p[lane];
            a1b += p1 * v1p[lane + 32];
            a2a += p2 * v2p[lane];
            a2b += p2 * v2p[lane + 32];
        }
    }
    float inv1 = 1.f / sum1, inv2 = 1.f / sum2;
    float lam = log1pf(expf(lambda_p[h]));

    float oa = a1a * inv1 - lam * (a2a * inv2);
    float ob = a1b * inv1 - lam * (a2b * inv2);

    float* dst = g_ctx + (size_t)(b * N_ + n) * DIM_ + h * 64;
    dst[lane]      = oa;
    dst[lane + 32] = ob;
}

// ---------------------------------------------------------------------------
// Launch
// ---------------------------------------------------------------------------
extern "C" void kernel_launch(void* const* d_in, const int* in_sizes, int n_in,
                              void* d_out, int out_size)
{
    const float* x      = (const float*)d_in[0];
    const float* Wq     = (const float*)d_in[1];
    const float* Wk     = (const float*)d_in[2];
    const float* Wv1    = (const float*)d_in[3];
    const float* Wv2    = (const float*)d_in[4];
    const float* lam_p  = (const float*)d_in[5];
    const float* Wo     = (const float*)d_in[6];
    const float* bo     = (const float*)d_in[7];
    float* out = (float*)d_out;

    float *qb, *kb, *v1b, *v2b, *ctx;
    cudaGetSymbolAddress((void**)&qb,  g_q);
    cudaGetSymbolAddress((void**)&kb,  g_k);
    cudaGetSymbolAddress((void**)&v1b, g_v1);
    cudaGetSymbolAddress((void**)&v2b, g_v2);
    cudaGetSymbolAddress((void**)&ctx, g_ctx);

    // projections (tf32 tensor cores)
    {
        dim3 t(256);
        gemm_tf32<<<dim3((2*DIM_)/TBN, M_ROWS/TBM), t>>>(x, Wq, nullptr, qb,  M_ROWS, 2*DIM_, DIM_);
        gemm_tf32<<<dim3(512/TBN,      M_ROWS/TBM), t>>>(x, Wk, nullptr, kb,  M_ROWS, 512, DIM_);
        gemm_tf32<<<dim3(256/TBN,      M_ROWS/TBM), t>>>(x, Wv1, nullptr, v1b, M_ROWS, 256, DIM_);
        gemm_tf32<<<dim3(256/TBN,      M_ROWS/TBM), t>>>(x, Wv2, nullptr, v2b, M_ROWS, 256, DIM_);
    }

    // RoPE + qk-norm
    {
        int qvec = M_ROWS * 24;
        int kvec = M_ROWS * 8;
        rope_norm<<<(qvec * 32 + 255) / 256, 256>>>(qb, 24, 2 * DIM_, qvec);
        rope_norm<<<(kvec * 32 + 255) / 256, 256>>>(kb, 8, 512, kvec);
    }

    // windowed differential attention
    {
        int total_q = B_ * H_ * N_;
        attn_kernel<<<total_q / AW, AW * 32>>>(lam_p);
    }

    // output projection + bias (tf32)
    gemm_tf32<<<dim3(DIM_/TBN, M_ROWS/TBM), 256>>>(ctx, Wo, bo, out, M_ROWS, DIM_, DIM_);
}

// round 3
// speedup vs baseline: 5.2720x; 3.7796x over previous
#include <cuda_runtime.h>
#include <math.h>
#include <stdint.h>

// Problem constants
#define B_    4
#define N_    1024
#define DIM_  768
#define H_    12
#define KV_   4
#define D_    64
#define SIDE_ 32
#define WIN_  8
#define REP_  (H_ / KV_)       // 3
#define M_ROWS (B_ * N_)       // 4096

// ---------------------------------------------------------------------------
// Scratch
// ---------------------------------------------------------------------------
__device__ float g_q  [M_ROWS * 2 * DIM_];   // 4096 x 1536
__device__ float g_k  [M_ROWS * 512];        // 4096 x 512  (k1 | k2 per kv head block of 64)
__device__ float g_v1 [M_ROWS * 256];
__device__ float g_v2 [M_ROWS * 256];
__device__ float g_ctx[M_ROWS * DIM_];

// ---------------------------------------------------------------------------
// Common PTX helpers
// ---------------------------------------------------------------------------
__device__ __forceinline__ float to_tf32(float x) {
    asm("cvt.rna.tf32.f32 %0, %0;" : "+f"(x));
    return x;
}
__device__ __forceinline__ uint32_t f2tf(float x) {
    asm("cvt.rna.tf32.f32 %0, %0;" : "+f"(x));
    return __float_as_uint(x);
}
__device__ __forceinline__ void mma_tf32(float* c, const uint32_t* a, const uint32_t* b) {
    asm volatile(
        "mma.sync.aligned.m16n8k8.row.col.f32.tf32.tf32.f32 "
        "{%0,%1,%2,%3}, {%4,%5,%6,%7}, {%8,%9}, {%0,%1,%2,%3};\n"
        : "+f"(c[0]), "+f"(c[1]), "+f"(c[2]), "+f"(c[3])
        : "r"(a[0]), "r"(a[1]), "r"(a[2]), "r"(a[3]), "r"(b[0]), "r"(b[1]));
}
__device__ __forceinline__ void cpa16(float* dst, const float* src) {
    unsigned u = (unsigned)__cvta_generic_to_shared(dst);
    asm volatile("cp.async.cg.shared.global [%0], [%1], 16;\n" :: "r"(u), "l"(src));
}

// ---------------------------------------------------------------------------
// TF32 tensor-core GEMM: C[M,N] = A[M,K] * W[N,K]^T (+bias)  (unchanged, validated)
// ---------------------------------------------------------------------------
#define TBM 128
#define TBN 64
#define TBK 32

__global__ __launch_bounds__(256)
void gemm_tf32(const float* __restrict__ A, const float* __restrict__ W,
               const float* __restrict__ bias, float* __restrict__ C,
               int M, int N, int K)
{
    __shared__ float As[TBK][TBM + 4];
    __shared__ float Ws[TBN][TBK + 4];

    const int tid  = threadIdx.x;
    const int lane = tid & 31;
    const int warp = tid >> 5;
    const int wm   = warp >> 1;
    const int wn   = warp & 1;
    const int gid  = lane >> 2;
    const int tig  = lane & 3;

    const int m0 = blockIdx.y * TBM;
    const int n0 = blockIdx.x * TBN;

    const int arow = tid >> 3;
    const int acol = (tid & 7) * 4;

    float acc[2][4][4];
#pragma unroll
    for (int i = 0; i < 2; i++)
#pragma unroll
        for (int j = 0; j < 4; j++)
#pragma unroll
            for (int l = 0; l < 4; l++) acc[i][j][l] = 0.f;

    const int nkt = K / TBK;
    float4 pA[4], pW[2];

#pragma unroll
    for (int i = 0; i < 4; i++)
        pA[i] = *reinterpret_cast<const float4*>(A + (size_t)(m0 + arow + 32 * i) * K + acol);
#pragma unroll
    for (int i = 0; i < 2; i++)
        pW[i] = *reinterpret_cast<const float4*>(W + (size_t)(n0 + arow + 32 * i) * K + acol);

    for (int kt = 0; kt < nkt; kt++) {
#pragma unroll
        for (int i = 0; i < 4; i++) {
            int r = arow + 32 * i;
            As[acol + 0][r] = to_tf32(pA[i].x);
            As[acol + 1][r] = to_tf32(pA[i].y);
            As[acol + 2][r] = to_tf32(pA[i].z);
            As[acol + 3][r] = to_tf32(pA[i].w);
        }
#pragma unroll
        for (int i = 0; i < 2; i++) {
            float4 v = pW[i];
            v.x = to_tf32(v.x); v.y = to_tf32(v.y);
            v.z = to_tf32(v.z); v.w = to_tf32(v.w);
            *reinterpret_cast<float4*>(&Ws[arow + 32 * i][acol]) = v;
        }
        __syncthreads();

        if (kt + 1 < nkt) {
            int kb = (kt + 1) * TBK;
#pragma unroll
            for (int i = 0; i < 4; i++)
                pA[i] = *reinterpret_cast<const float4*>(A + (size_t)(m0 + arow + 32 * i) * K + kb + acol);
#pragma unroll
            for (int i = 0; i < 2; i++)
                pW[i] = *reinterpret_cast<const float4*>(W + (size_t)(n0 + arow + 32 * i) * K + kb + acol);
        }

#pragma unroll
        for (int ks = 0; ks < 4; ks++) {
            const int kk = ks * 8;
            uint32_t a[2][4], b[4][2];
#pragma unroll
            for (int mt = 0; mt < 2; mt++) {
                int m = wm * 32 + mt * 16 + gid;
                a[mt][0] = __float_as_uint(As[kk + tig][m]);
                a[mt][1] = __float_as_uint(As[kk + tig][m + 8]);
                a[mt][2] = __float_as_uint(As[kk + tig + 4][m]);
                a[mt][3] = __float_as_uint(As[kk + tig + 4][m + 8]);
            }
#pragma unroll
            for (int nt = 0; nt < 4; nt++) {
                int n = wn * 32 + nt * 8 + gid;
                b[nt][0] = __float_as_uint(Ws[n][kk + tig]);
                b[nt][1] = __float_as_uint(Ws[n][kk + tig + 4]);
            }
#pragma unroll
            for (int mt = 0; mt < 2; mt++)
#pragma unroll
                for (int nt = 0; nt < 4; nt++)
                    mma_tf32(acc[mt][nt], a[mt], b[nt]);
        }
        __syncthreads();
    }

#pragma unroll
    for (int mt = 0; mt < 2; mt++) {
        int m = m0 + wm * 32 + mt * 16 + gid;
#pragma unroll
        for (int nt = 0; nt < 4; nt++) {
            int n = n0 + wn * 32 + nt * 8 + 2 * tig;
            float b0 = bias ? bias[n] : 0.f;
            float b1 = bias ? bias[n + 1] : 0.f;
            float2 r0 = make_float2(acc[mt][nt][0] + b0, acc[mt][nt][1] + b1);
            float2 r1 = make_float2(acc[mt][nt][2] + b0, acc[mt][nt][3] + b1);
            *reinterpret_cast<float2*>(C + (size_t)m * N + n) = r0;
            *reinterpret_cast<float2*>(C + (size_t)(m + 8) * N + n) = r1;
        }
    }
}

// ---------------------------------------------------------------------------
// 2D RoPE + qk-norm (one warp per 64-vector).
// ---------------------------------------------------------------------------
__global__ __launch_bounds__(256)
void rope_norm(float* __restrict__ buf, int vpr, int stride, int total_vec)
{
    const int gw   = (blockIdx.x * blockDim.x + threadIdx.x) >> 5;
    const int lane = threadIdx.x & 31;
    if (gw >= total_vec) return;

    const int row = gw / vpr;
    const int vec = gw - row * vpr;
    const int n   = row & (N_ - 1);
    const float ph = (float)(n >> 5);
    const float pw = (float)(n & 31);

    float* p = buf + (size_t)row * stride + vec * 64;
    float x0 = p[lane];
    float x1 = p[lane + 32];

    float inv = exp2f((float)lane * -0.4152410118609203f);
    float t0 = ph * inv, t1 = pw * inv;
    float c0, s0, c1, s1;
    sincosf(t0, &s0, &c0);
    sincosf(t1, &s1, &c1);

    float px0 = __shfl_xor_sync(0xffffffffu, x0, 1);
    float px1 = __shfl_xor_sync(0xffffffffu, x1, 1);
    float r0 = (lane & 1) ? px0 : -px0;
    float r1 = (lane & 1) ? px1 : -px1;

    float o0 = x0 * c0 + r0 * s0;
    float o1 = x1 * c1 + r1 * s1;

    float ss = o0 * o0 + o1 * o1;
#pragma unroll
    for (int o = 16; o; o >>= 1) ss += __shfl_xor_sync(0xffffffffu, ss, o);
    float sc = 1.f / (sqrtf(ss) + 1e-6f);

    p[lane]      = o0 * sc;
    p[lane + 32] = o1 * sc;
}

// ---------------------------------------------------------------------------
// Tensor-core windowed differential flash attention.
// Block = (b, kh, ph): 512 blocks, 6 warps. Warp = (side, head).
// Each warp: 32 queries (the 32 positions in grid row ph) x 64 dims.
// Iterate over key grid rows [ph-8, ph+8] (clipped), 32 keys per tile,
// K/V tiles cp.async double-buffered in smem, shared by all warps.
//
// smem: sKV [2 stages][4 arrays: k1,k2,v1,v2][32 keys][68]  = 17408 floats
//       sP  [6 warps][32][36]                                =  6912 floats
// total 24320 floats = 97280 B (dynamic)
// ---------------------------------------------------------------------------
#define ATT_SMEM_FLOATS (17408 + 6912)
#define ATT_SMEM_BYTES  (ATT_SMEM_FLOATS * 4)

__global__ __launch_bounds__(192)
void attn_tc(const float* __restrict__ lambda_p)
{
    extern __shared__ float sm[];
    float* sKV = sm;            // [2][4][32][68]
    float* sP  = sm + 17408;    // [6][32][36]

    const int tid  = threadIdx.x;
    const int lane = tid & 31;
    const int warp = tid >> 5;           // 0..5
    const int gid  = lane >> 2;          // 0..7
    const int tig  = lane & 3;           // 0..3

    const int blk = blockIdx.x;          // ((b*4 + kh)*32 + ph)
    const int ph  = blk & 31;
    const int kh  = (blk >> 5) & 3;
    const int b   = blk >> 7;

    const int side = warp / 3;           // 0 or 1
    const int hloc = warp - side * 3;    // 0..2
    const int h    = kh * 3 + hloc;

    const int rlo = max(ph - WIN_, 0);
    const int rhi = min(ph + WIN_, SIDE_ - 1);
    const int nit = rhi - rlo + 1;

    // stage loader: 2048 float4 chunks across 192 threads
    auto load_stage = [&](int st, int r) {
#pragma unroll
        for (int i = 0; i < 11; i++) {
            int idx = tid + i * 192;
            if (idx < 2048) {
                int arr = idx >> 9;
                int key = (idx >> 4) & 31;
                int f4  = (idx & 15) * 4;
                size_t row = (size_t)(b * N_ + r * 32 + key);
                const float* src;
                if (arr == 0)      src = g_k  + row * 512       + kh * 64 + f4;
                else if (arr == 1) src = g_k  + row * 512 + 256 + kh * 64 + f4;
                else if (arr == 2) src = g_v1 + row * 256       + kh * 64 + f4;
                else               src = g_v2 + row * 256       + kh * 64 + f4;
                cpa16(sKV + ((size_t)(st * 4 + arr) * 32 + key) * 68 + f4, src);
            }
        }
        asm volatile("cp.async.commit_group;\n" ::: "memory");
    };

    load_stage(0, rlo);

    // Q fragments (tf32), loaded straight from global while stage 0 flies
    uint32_t qf[2][8][4];
    {
        const float* qb = g_q + ((size_t)(b * N_ + ph * 32)) * 1536 + side * 768 + h * 64;
#pragma unroll
        for (int mt = 0; mt < 2; mt++) {
            const float* q0 = qb + (size_t)(mt * 16 + gid) * 1536;
            const float* q1 = q0 + (size_t)8 * 1536;
#pragma unroll
            for (int kt = 0; kt < 8; kt++) {
                qf[mt][kt][0] = f2tf(q0[kt * 8 + tig]);
                qf[mt][kt][1] = f2tf(q1[kt * 8 + tig]);
                qf[mt][kt][2] = f2tf(q0[kt * 8 + tig + 4]);
                qf[mt][kt][3] = f2tf(q1[kt * 8 + tig + 4]);
            }
        }
    }

    float o[2][8][4];
#pragma unroll
    for (int mt = 0; mt < 2; mt++)
#pragma unroll
        for (int nt = 0; nt < 8; nt++)
#pragma unroll
            for (int c = 0; c < 4; c++) o[mt][nt][c] = 0.f;

    float m_[2][2] = {{-1e30f, -1e30f}, {-1e30f, -1e30f}};
    float l_[2][2] = {{0.f, 0.f}, {0.f, 0.f}};

    float* sPw = sP + warp * 1152;       // [32][36]

    asm volatile("cp.async.wait_group 0;\n" ::: "memory");
    __syncthreads();

    for (int it = 0; it < nit; it++) {
        const int cur = it & 1;
        if (it + 1 < nit) load_stage(cur ^ 1, rlo + it + 1);

        const float* K = sKV + (size_t)(cur * 4 + side) * 32 * 68;
        const float* V = sKV + (size_t)(cur * 4 + 2 + side) * 32 * 68;

        // ---- S = Q @ K^T  (32 queries x 32 keys)
        float s[2][4][4];
#pragma unroll
        for (int mt = 0; mt < 2; mt++)
#pragma unroll
            for (int nt = 0; nt < 4; nt++)
#pragma unroll
                for (int c = 0; c < 4; c++) s[mt][nt][c] = 0.f;

#pragma unroll
        for (int kt = 0; kt < 8; kt++) {
            uint32_t bf[4][2];
#pragma unroll
            for (int nt = 0; nt < 4; nt++) {
                bf[nt][0] = f2tf(K[(nt * 8 + gid) * 68 + kt * 8 + tig]);
                bf[nt][1] = f2tf(K[(nt * 8 + gid) * 68 + kt * 8 + tig + 4]);
            }
#pragma unroll
            for (int mt = 0; mt < 2; mt++)
#pragma unroll
                for (int nt = 0; nt < 4; nt++)
                    mma_tf32(s[mt][nt], qf[mt][kt], bf[nt]);
        }

        // ---- scale + column mask + running max
        float mnew[2][2] = {{m_[0][0], m_[0][1]}, {m_[1][0], m_[1][1]}};
#pragma unroll
        for (int mt = 0; mt < 2; mt++)
#pragma unroll
            for (int nt = 0; nt < 4; nt++)
#pragma unroll
                for (int c = 0; c < 4; c++) {
                    int half = c >> 1;
                    int pw = mt * 16 + gid + half * 8;
                    int ck = nt * 8 + 2 * tig + (c & 1);
                    float v = s[mt][nt][c] * 0.125f;
                    int d = pw - ck; d = (d < 0) ? -d : d;
                    v = (d > WIN_) ? -1e30f : v;
                    s[mt][nt][c] = v;
                    mnew[mt][half] = fmaxf(mnew[mt][half], v);
                }
#pragma unroll
        for (int mt = 0; mt < 2; mt++)
#pragma unroll
            for (int hf = 0; hf < 2; hf++) {
                float mm = mnew[mt][hf];
                mm = fmaxf(mm, __shfl_xor_sync(0xffffffffu, mm, 1));
                mm = fmaxf(mm, __shfl_xor_sync(0xffffffffu, mm, 2));
                mnew[mt][hf] = mm;
            }

        float scl[2][2];
#pragma unroll
        for (int mt = 0; mt < 2; mt++)
#pragma unroll
            for (int hf = 0; hf < 2; hf++) {
                scl[mt][hf] = __expf(m_[mt][hf] - mnew[mt][hf]);
                m_[mt][hf] = mnew[mt][hf];
            }

        // ---- exp, write P tile, accumulate row sums
        __syncwarp();
        float rs[2][2] = {{0.f, 0.f}, {0.f, 0.f}};
#pragma unroll
        for (int mt = 0; mt < 2; mt++)
#pragma unroll
            for (int nt = 0; nt < 4; nt++) {
                float p0 = __expf(s[mt][nt][0] - m_[mt][0]);
                float p1 = __expf(s[mt][nt][1] - m_[mt][0]);
                float p2 = __expf(s[mt][nt][2] - m_[mt][1]);
                float p3 = __expf(s[mt][nt][3] - m_[mt][1]);
                rs[mt][0] += p0 + p1;
                rs[mt][1] += p2 + p3;
                int r0 = mt * 16 + gid, r1 = r0 + 8, cc = nt * 8 + 2 * tig;
                sPw[r0 * 36 + cc]     = __uint_as_float(f2tf(p0));
                sPw[r0 * 36 + cc + 1] = __uint_as_float(f2tf(p1));
                sPw[r1 * 36 + cc]     = __uint_as_float(f2tf(p2));
                sPw[r1 * 36 + cc + 1] = __uint_as_float(f2tf(p3));
            }
#pragma unroll
        for (int mt = 0; mt < 2; mt++)
#pragma unroll
            for (int hf = 0; hf < 2; hf++) {
                float r = rs[mt][hf];
                r += __shfl_xor_sync(0xffffffffu, r, 1);
                r += __shfl_xor_sync(0xffffffffu, r, 2);
                l_[mt][hf] = l_[mt][hf] * scl[mt][hf] + r;
            }
        // rescale O
#pragma unroll
        for (int mt = 0; mt < 2; mt++)
#pragma unroll
            for (int nt = 0; nt < 8; nt++) {
                o[mt][nt][0] *= scl[mt][0];
                o[mt][nt][1] *= scl[mt][0];
                o[mt][nt][2] *= scl[mt][1];
                o[mt][nt][3] *= scl[mt][1];
            }

        __syncwarp();

        // ---- O += P @ V  (32 queries x 64 dims, k = 32 keys)
#pragma unroll
        for (int kt = 0; kt < 4; kt++) {
            uint32_t af[2][4];
#pragma unroll
            for (int mt = 0; mt < 2; mt++) {
                int r0 = mt * 16 + gid;
                af[mt][0] = __float_as_uint(sPw[r0 * 36 + kt * 8 + tig]);
                af[mt][1] = __float_as_uint(sPw[(r0 + 8) * 36 + kt * 8 + tig]);
                af[mt][2] = __float_as_uint(sPw[r0 * 36 + kt * 8 + tig + 4]);
                af[mt][3] = __float_as_uint(sPw[(r0 + 8) * 36 + kt * 8 + tig + 4]);
            }
#pragma unroll
            for (int nt = 0; nt < 8; nt++) {
                uint32_t bf[2];
                bf[0] = f2tf(V[(kt * 8 + tig) * 68 + nt * 8 + gid]);
                bf[1] = f2tf(V[(kt * 8 + tig + 4) * 68 + nt * 8 + gid]);
                mma_tf32(o[0][nt], af[0], bf);
                mma_tf32(o[1][nt], af[1], bf);
            }
        }

        asm volatile("cp.async.wait_group 0;\n" ::: "memory");
        __syncthreads();
    }

    // ---- combine sides: out = O1/l1 - softplus(lambda) * O2/l2
    float lam = log1pf(__expf(lambda_p[h]));
    float inv[2][2] = {{1.f / l_[0][0], 1.f / l_[0][1]},
                       {1.f / l_[1][0], 1.f / l_[1][1]}};

    __syncthreads();   // all P-tile reads done before reuse as O2 buffer
    if (side == 1) {
        float* sO2 = sP + hloc * 2176;   // [32][68]
#pragma unroll
        for (int mt = 0; mt < 2; mt++)
#pragma unroll
            for (int nt = 0; nt < 8; nt++) {
                int r0 = mt * 16 + gid, r1 = r0 + 8, cc = nt * 8 + 2 * tig;
                sO2[r0 * 68 + cc]     = o[mt][nt][0] * inv[mt][0];
                sO2[r0 * 68 + cc + 1] = o[mt][nt][1] * inv[mt][0];
                sO2[r1 * 68 + cc]     = o[mt][nt][2] * inv[mt][1];
                sO2[r1 * 68 + cc + 1] = o[mt][nt][3] * inv[mt][1];
            }
    }
    __syncthreads();
    if (side == 0) {
        const float* sO2 = sP + hloc * 2176;
        float* dst = g_ctx + ((size_t)(b * N_ + ph * 32)) * 768 + h * 64;
#pragma unroll
        for (int mt = 0; mt < 2; mt++)
#pragma unroll
            for (int nt = 0; nt < 8; nt++) {
                int r0 = mt * 16 + gid, r1 = r0 + 8, cc = nt * 8 + 2 * tig;
                float2 v0, v1;
                v0.x = o[mt][nt][0] * inv[mt][0] - lam * sO2[r0 * 68 + cc];
                v0.y = o[mt][nt][1] * inv[mt][0] - lam * sO2[r0 * 68 + cc + 1];
                v1.x = o[mt][nt][2] * inv[mt][1] - lam * sO2[r1 * 68 + cc];
                v1.y = o[mt][nt][3] * inv[mt][1] - lam * sO2[r1 * 68 + cc + 1];
                *reinterpret_cast<float2*>(dst + (size_t)r0 * 768 + cc) = v0;
                *reinterpret_cast<float2*>(dst + (size_t)r1 * 768 + cc) = v1;
            }
    }
}

// ---------------------------------------------------------------------------
// Launch
// ---------------------------------------------------------------------------
extern "C" void kernel_launch(void* const* d_in, const int* in_sizes, int n_in,
                              void* d_out, int out_size)
{
    const float* x      = (const float*)d_in[0];
    const float* Wq     = (const float*)d_in[1];
    const float* Wk     = (const float*)d_in[2];
    const float* Wv1    = (const float*)d_in[3];
    const float* Wv2    = (const float*)d_in[4];
    const float* lam_p  = (const float*)d_in[5];
    const float* Wo     = (const float*)d_in[6];
    const float* bo     = (const float*)d_in[7];
    float* out = (float*)d_out;

    float *qb, *kb, *v1b, *v2b, *ctx;
    cudaGetSymbolAddress((void**)&qb,  g_q);
    cudaGetSymbolAddress((void**)&kb,  g_k);
    cudaGetSymbolAddress((void**)&v1b, g_v1);
    cudaGetSymbolAddress((void**)&v2b, g_v2);
    cudaGetSymbolAddress((void**)&ctx, g_ctx);

    cudaFuncSetAttribute(attn_tc, cudaFuncAttributeMaxDynamicSharedMemorySize,
                         ATT_SMEM_BYTES);

    // projections (tf32 tensor cores)
    {
        dim3 t(256);
        gemm_tf32<<<dim3((2*DIM_)/TBN, M_ROWS/TBM), t>>>(x, Wq, nullptr, qb,  M_ROWS, 2*DIM_, DIM_);
        gemm_tf32<<<dim3(512/TBN,      M_ROWS/TBM), t>>>(x, Wk, nullptr, kb,  M_ROWS, 512, DIM_);
        gemm_tf32<<<dim3(256/TBN,      M_ROWS/TBM), t>>>(x, Wv1, nullptr, v1b, M_ROWS, 256, DIM_);
        gemm_tf32<<<dim3(256/TBN,      M_ROWS/TBM), t>>>(x, Wv2, nullptr, v2b, M_ROWS, 256, DIM_);
    }

    // RoPE + qk-norm
    {
        int qvec = M_ROWS * 24;
        int kvec = M_ROWS * 8;
        rope_norm<<<(qvec * 32 + 255) / 256, 256>>>(qb, 24, 2 * DIM_, qvec);
        rope_norm<<<(kvec * 32 + 255) / 256, 256>>>(kb, 8, 512, kvec);
    }

    // tensor-core windowed differential attention
    attn_tc<<<B_ * KV_ * SIDE_, 192, ATT_SMEM_BYTES>>>(lam_p);

    // output projection + bias (tf32)
    gemm_tf32<<<dim3(DIM_/TBN, M_ROWS/TBM), 256>>>(ctx, Wo, bo, out, M_ROWS, DIM_, DIM_);
}

// round 4
// speedup vs baseline: 5.6975x; 1.0807x over previous
#include <cuda_runtime.h>
#include <math.h>
#include <stdint.h>

// Problem constants
#define B_    4
#define N_    1024
#define DIM_  768
#define H_    12
#define KV_   4
#define D_    64
#define SIDE_ 32
#define WIN_  8
#define REP_  (H_ / KV_)       // 3
#define M_ROWS (B_ * N_)       // 4096

// Fused projection layout: [row][2560] = q(0..1535) | k(1536..2047) | v1(2048..2303) | v2(2304..2559)
#define PROJ_N 2560
#define OFF_K  1536
#define OFF_V1 2048
#define OFF_V2 2304

// ---------------------------------------------------------------------------
// Scratch
// ---------------------------------------------------------------------------
__device__ float g_proj[M_ROWS * PROJ_N];    // 40 MB
__device__ float g_ctx [M_ROWS * DIM_];      // 12 MB

// ---------------------------------------------------------------------------
// Common PTX helpers
// ---------------------------------------------------------------------------
__device__ __forceinline__ float to_tf32(float x) {
    asm("cvt.rna.tf32.f32 %0, %0;" : "+f"(x));
    return x;
}
__device__ __forceinline__ uint32_t f2tf(float x) {
    asm("cvt.rna.tf32.f32 %0, %0;" : "+f"(x));
    return __float_as_uint(x);
}
__device__ __forceinline__ void mma_tf32(float* c, const uint32_t* a, const uint32_t* b) {
    asm volatile(
        "mma.sync.aligned.m16n8k8.row.col.f32.tf32.tf32.f32 "
        "{%0,%1,%2,%3}, {%4,%5,%6,%7}, {%8,%9}, {%0,%1,%2,%3};\n"
        : "+f"(c[0]), "+f"(c[1]), "+f"(c[2]), "+f"(c[3])
        : "r"(a[0]), "r"(a[1]), "r"(a[2]), "r"(a[3]), "r"(b[0]), "r"(b[1]));
}
__device__ __forceinline__ void cpa16(float* dst, const float* src) {
    unsigned u = (unsigned)__cvta_generic_to_shared(dst);
    asm volatile("cp.async.cg.shared.global [%0], [%1], 16;\n" :: "r"(u), "l"(src));
}

// ---------------------------------------------------------------------------
// TF32 tensor-core GEMM with 4-way weight routing on column block:
//   cols [0, 1536)      -> W0
//   cols [1536, 2048)   -> W1
//   cols [2048, 2304)   -> W2
//   cols [2304, ...)    -> W3
// C[M,N] = A[M,K] * Wsel[.,K]^T (+bias). For a plain GEMM pass the same W
// pointer 4x (N<=1536 keeps it in the first branch).
// ---------------------------------------------------------------------------
#define TBM 128
#define TBN 64
#define TBK 32

__global__ __launch_bounds__(256)
void gemm_tf32(const float* __restrict__ A,
               const float* __restrict__ W0, const float* __restrict__ W1,
               const float* __restrict__ W2, const float* __restrict__ W3,
               const float* __restrict__ bias, float* __restrict__ C,
               int M, int N, int K)
{
    __shared__ float As[TBK][TBM + 4];
    __shared__ float Ws[TBN][TBK + 4];

    const int tid  = threadIdx.x;
    const int lane = tid & 31;
    const int warp = tid >> 5;
    const int wm   = warp >> 1;
    const int wn   = warp & 1;
    const int gid  = lane >> 2;
    const int tig  = lane & 3;

    const int m0 = blockIdx.y * TBM;
    const int n0 = blockIdx.x * TBN;

    // weight routing (uniform per block)
    const float* W;
    int nw;
    if (n0 < OFF_K)       { W = W0; nw = n0; }
    else if (n0 < OFF_V1) { W = W1; nw = n0 - OFF_K; }
    else if (n0 < OFF_V2) { W = W2; nw = n0 - OFF_V1; }
    else                  { W = W3; nw = n0 - OFF_V2; }

    const int arow = tid >> 3;
    const int acol = (tid & 7) * 4;

    float acc[2][4][4];
#pragma unroll
    for (int i = 0; i < 2; i++)
#pragma unroll
        for (int j = 0; j < 4; j++)
#pragma unroll
            for (int l = 0; l < 4; l++) acc[i][j][l] = 0.f;

    const int nkt = K / TBK;
    float4 pA[4], pW[2];

#pragma unroll
    for (int i = 0; i < 4; i++)
        pA[i] = *reinterpret_cast<const float4*>(A + (size_t)(m0 + arow + 32 * i) * K + acol);
#pragma unroll
    for (int i = 0; i < 2; i++)
        pW[i] = *reinterpret_cast<const float4*>(W + (size_t)(nw + arow + 32 * i) * K + acol);

    for (int kt = 0; kt < nkt; kt++) {
#pragma unroll
        for (int i = 0; i < 4; i++) {
            int r = arow + 32 * i;
            As[acol + 0][r] = to_tf32(pA[i].x);
            As[acol + 1][r] = to_tf32(pA[i].y);
            As[acol + 2][r] = to_tf32(pA[i].z);
            As[acol + 3][r] = to_tf32(pA[i].w);
        }
#pragma unroll
        for (int i = 0; i < 2; i++) {
            float4 v = pW[i];
            v.x = to_tf32(v.x); v.y = to_tf32(v.y);
            v.z = to_tf32(v.z); v.w = to_tf32(v.w);
            *reinterpret_cast<float4*>(&Ws[arow + 32 * i][acol]) = v;
        }
        __syncthreads();

        if (kt + 1 < nkt) {
            int kb = (kt + 1) * TBK;
#pragma unroll
            for (int i = 0; i < 4; i++)
                pA[i] = *reinterpret_cast<const float4*>(A + (size_t)(m0 + arow + 32 * i) * K + kb + acol);
#pragma unroll
            for (int i = 0; i < 2; i++)
                pW[i] = *reinterpret_cast<const float4*>(W + (size_t)(nw + arow + 32 * i) * K + kb + acol);
        }

#pragma unroll
        for (int ks = 0; ks < 4; ks++) {
            const int kk = ks * 8;
            uint32_t a[2][4], b[4][2];
#pragma unroll
            for (int mt = 0; mt < 2; mt++) {
                int m = wm * 32 + mt * 16 + gid;
                a[mt][0] = __float_as_uint(As[kk + tig][m]);
                a[mt][1] = __float_as_uint(As[kk + tig][m + 8]);
                a[mt][2] = __float_as_uint(As[kk + tig + 4][m]);
                a[mt][3] = __float_as_uint(As[kk + tig + 4][m + 8]);
            }
#pragma unroll
            for (int nt = 0; nt < 4; nt++) {
                int n = wn * 32 + nt * 8 + gid;
                b[nt][0] = __float_as_uint(Ws[n][kk + tig]);
                b[nt][1] = __float_as_uint(Ws[n][kk + tig + 4]);
            }
#pragma unroll
            for (int mt = 0; mt < 2; mt++)
#pragma unroll
                for (int nt = 0; nt < 4; nt++)
                    mma_tf32(acc[mt][nt], a[mt], b[nt]);
        }
        __syncthreads();
    }

#pragma unroll
    for (int mt = 0; mt < 2; mt++) {
        int m = m0 + wm * 32 + mt * 16 + gid;
#pragma unroll
        for (int nt = 0; nt < 4; nt++) {
            int n = n0 + wn * 32 + nt * 8 + 2 * tig;
            float b0 = bias ? bias[n] : 0.f;
            float b1 = bias ? bias[n + 1] : 0.f;
            float2 r0 = make_float2(acc[mt][nt][0] + b0, acc[mt][nt][1] + b1);
            float2 r1 = make_float2(acc[mt][nt][2] + b0, acc[mt][nt][3] + b1);
            *reinterpret_cast<float2*>(C + (size_t)m * N + n) = r0;
            *reinterpret_cast<float2*>(C + (size_t)(m + 8) * N + n) = r1;
        }
    }
}

// ---------------------------------------------------------------------------
// 2D RoPE + qk-norm (one warp per 64-vector). q+k are contiguous 32 vecs/row.
// ---------------------------------------------------------------------------
__global__ __launch_bounds__(256)
void rope_norm(float* __restrict__ buf, int vpr, int stride, int total_vec)
{
    const int gw   = (blockIdx.x * blockDim.x + threadIdx.x) >> 5;
    const int lane = threadIdx.x & 31;
    if (gw >= total_vec) return;

    const int row = gw / vpr;
    const int vec = gw - row * vpr;
    const int n   = row & (N_ - 1);
    const float ph = (float)(n >> 5);
    const float pw = (float)(n & 31);

    float* p = buf + (size_t)row * stride + vec * 64;
    float x0 = p[lane];
    float x1 = p[lane + 32];

    float inv = exp2f((float)lane * -0.4152410118609203f);
    float t0 = ph * inv, t1 = pw * inv;
    float c0, s0, c1, s1;
    sincosf(t0, &s0, &c0);
    sincosf(t1, &s1, &c1);

    float px0 = __shfl_xor_sync(0xffffffffu, x0, 1);
    float px1 = __shfl_xor_sync(0xffffffffu, x1, 1);
    float r0 = (lane & 1) ? px0 : -px0;
    float r1 = (lane & 1) ? px1 : -px1;

    float o0 = x0 * c0 + r0 * s0;
    float o1 = x1 * c1 + r1 * s1;

    float ss = o0 * o0 + o1 * o1;
#pragma unroll
    for (int o = 16; o; o >>= 1) ss += __shfl_xor_sync(0xffffffffu, ss, o);
    float sc = 1.f / (sqrtf(ss) + 1e-6f);

    p[lane]      = o0 * sc;
    p[lane + 32] = o1 * sc;
}

// ---------------------------------------------------------------------------
// Tensor-core windowed differential flash attention (reads g_proj).
// Block = (b, kh, ph): 512 blocks, 6 warps. Warp = (side, head).
// ---------------------------------------------------------------------------
#define ATT_SMEM_FLOATS (17408 + 6912)
#define ATT_SMEM_BYTES  (ATT_SMEM_FLOATS * 4)

__global__ __launch_bounds__(192)
void attn_tc(const float* __restrict__ lambda_p)
{
    extern __shared__ float sm[];
    float* sKV = sm;            // [2][4][32][68]
    float* sP  = sm + 17408;    // [6][32][36]

    const int tid  = threadIdx.x;
    const int lane = tid & 31;
    const int warp = tid >> 5;
    const int gid  = lane >> 2;
    const int tig  = lane & 3;

    const int blk = blockIdx.x;
    const int ph  = blk & 31;
    const int kh  = (blk >> 5) & 3;
    const int b   = blk >> 7;

    const int side = warp / 3;
    const int hloc = warp - side * 3;
    const int h    = kh * 3 + hloc;

    const int rlo = max(ph - WIN_, 0);
    const int rhi = min(ph + WIN_, SIDE_ - 1);
    const int nit = rhi - rlo + 1;

    // stage loader: arrays k1,k2,v1,v2 live at proj cols 1536 + arr*256 + kh*64
    auto load_stage = [&](int st, int r) {
#pragma unroll
        for (int i = 0; i < 11; i++) {
            int idx = tid + i * 192;
            if (idx < 2048) {
                int arr = idx >> 9;
                int key = (idx >> 4) & 31;
                int f4  = (idx & 15) * 4;
                const float* src = g_proj + (size_t)(b * N_ + r * 32 + key) * PROJ_N
                                 + OFF_K + arr * 256 + kh * 64 + f4;
                cpa16(sKV + ((size_t)(st * 4 + arr) * 32 + key) * 68 + f4, src);
            }
        }
        asm volatile("cp.async.commit_group;\n" ::: "memory");
    };

    load_stage(0, rlo);

    // Q fragments (tf32)
    uint32_t qf[2][8][4];
    {
        const float* qb = g_proj + ((size_t)(b * N_ + ph * 32)) * PROJ_N + side * 768 + h * 64;
#pragma unroll
        for (int mt = 0; mt < 2; mt++) {
            const float* q0 = qb + (size_t)(mt * 16 + gid) * PROJ_N;
            const float* q1 = q0 + (size_t)8 * PROJ_N;
#pragma unroll
            for (int kt = 0; kt < 8; kt++) {
                qf[mt][kt][0] = f2tf(q0[kt * 8 + tig]);
                qf[mt][kt][1] = f2tf(q1[kt * 8 + tig]);
                qf[mt][kt][2] = f2tf(q0[kt * 8 + tig + 4]);
                qf[mt][kt][3] = f2tf(q1[kt * 8 + tig + 4]);
            }
        }
    }

    float o[2][8][4];
#pragma unroll
    for (int mt = 0; mt < 2; mt++)
#pragma unroll
        for (int nt = 0; nt < 8; nt++)
#pragma unroll
            for (int c = 0; c < 4; c++) o[mt][nt][c] = 0.f;

    float m_[2][2] = {{-1e30f, -1e30f}, {-1e30f, -1e30f}};
    float l_[2][2] = {{0.f, 0.f}, {0.f, 0.f}};

    float* sPw = sP + warp * 1152;

    asm volatile("cp.async.wait_group 0;\n" ::: "memory");
    __syncthreads();

    for (int it = 0; it < nit; it++) {
        const int cur = it & 1;
        if (it + 1 < nit) load_stage(cur ^ 1, rlo + it + 1);

        const float* K = sKV + (size_t)(cur * 4 + side) * 32 * 68;
        const float* V = sKV + (size_t)(cur * 4 + 2 + side) * 32 * 68;

        float s[2][4][4];
#pragma unroll
        for (int mt = 0; mt < 2; mt++)
#pragma unroll
            for (int nt = 0; nt < 4; nt++)
#pragma unroll
                for (int c = 0; c < 4; c++) s[mt][nt][c] = 0.f;

#pragma unroll
        for (int kt = 0; kt < 8; kt++) {
            uint32_t bf[4][2];
#pragma unroll
            for (int nt = 0; nt < 4; nt++) {
                bf[nt][0] = f2tf(K[(nt * 8 + gid) * 68 + kt * 8 + tig]);
                bf[nt][1] = f2tf(K[(nt * 8 + gid) * 68 + kt * 8 + tig + 4]);
            }
#pragma unroll
            for (int mt = 0; mt < 2; mt++)
#pragma unroll
                for (int nt = 0; nt < 4; nt++)
                    mma_tf32(s[mt][nt], qf[mt][kt], bf[nt]);
        }

        float mnew[2][2] = {{m_[0][0], m_[0][1]}, {m_[1][0], m_[1][1]}};
#pragma unroll
        for (int mt = 0; mt < 2; mt++)
#pragma unroll
            for (int nt = 0; nt < 4; nt++)
#pragma unroll
                for (int c = 0; c < 4; c++) {
                    int half = c >> 1;
                    int pw = mt * 16 + gid + half * 8;
                    int ck = nt * 8 + 2 * tig + (c & 1);
                    float v = s[mt][nt][c] * 0.125f;
                    int d = pw - ck; d = (d < 0) ? -d : d;
                    v = (d > WIN_) ? -1e30f : v;
                    s[mt][nt][c] = v;
                    mnew[mt][half] = fmaxf(mnew[mt][half], v);
                }
#pragma unroll
        for (int mt = 0; mt < 2; mt++)
#pragma unroll
            for (int hf = 0; hf < 2; hf++) {
                float mm = mnew[mt][hf];
                mm = fmaxf(mm, __shfl_xor_sync(0xffffffffu, mm, 1));
                mm = fmaxf(mm, __shfl_xor_sync(0xffffffffu, mm, 2));
                mnew[mt][hf] = mm;
            }

        float scl[2][2];
#pragma unroll
        for (int mt = 0; mt < 2; mt++)
#pragma unroll
            for (int hf = 0; hf < 2; hf++) {
                scl[mt][hf] = __expf(m_[mt][hf] - mnew[mt][hf]);
                m_[mt][hf] = mnew[mt][hf];
            }

        __syncwarp();
        float rs[2][2] = {{0.f, 0.f}, {0.f, 0.f}};
#pragma unroll
        for (int mt = 0; mt < 2; mt++)
#pragma unroll
            for (int nt = 0; nt < 4; nt++) {
                float p0 = __expf(s[mt][nt][0] - m_[mt][0]);
                float p1 = __expf(s[mt][nt][1] - m_[mt][0]);
                float p2 = __expf(s[mt][nt][2] - m_[mt][1]);
                float p3 = __expf(s[mt][nt][3] - m_[mt][1]);
                rs[mt][0] += p0 + p1;
                rs[mt][1] += p2 + p3;
                int r0 = mt * 16 + gid, r1 = r0 + 8, cc = nt * 8 + 2 * tig;
                sPw[r0 * 36 + cc]     = __uint_as_float(f2tf(p0));
                sPw[r0 * 36 + cc + 1] = __uint_as_float(f2tf(p1));
                sPw[r1 * 36 + cc]     = __uint_as_float(f2tf(p2));
                sPw[r1 * 36 + cc + 1] = __uint_as_float(f2tf(p3));
            }
#pragma unroll
        for (int mt = 0; mt < 2; mt++)
#pragma unroll
            for (int hf = 0; hf < 2; hf++) {
                float r = rs[mt][hf];
                r += __shfl_xor_sync(0xffffffffu, r, 1);
                r += __shfl_xor_sync(0xffffffffu, r, 2);
                l_[mt][hf] = l_[mt][hf] * scl[mt][hf] + r;
            }
#pragma unroll
        for (int mt = 0; mt < 2; mt++)
#pragma unroll
            for (int nt = 0; nt < 8; nt++) {
                o[mt][nt][0] *= scl[mt][0];
                o[mt][nt][1] *= scl[mt][0];
                o[mt][nt][2] *= scl[mt][1];
                o[mt][nt][3] *= scl[mt][1];
            }

        __syncwarp();

#pragma unroll
        for (int kt = 0; kt < 4; kt++) {
            uint32_t af[2][4];
#pragma unroll
            for (int mt = 0; mt < 2; mt++) {
                int r0 = mt * 16 + gid;
                af[mt][0] = __float_as_uint(sPw[r0 * 36 + kt * 8 + tig]);
                af[mt][1] = __float_as_uint(sPw[(r0 + 8) * 36 + kt * 8 + tig]);
                af[mt][2] = __float_as_uint(sPw[r0 * 36 + kt * 8 + tig + 4]);
                af[mt][3] = __float_as_uint(sPw[(r0 + 8) * 36 + kt * 8 + tig + 4]);
            }
#pragma unroll
            for (int nt = 0; nt < 8; nt++) {
                uint32_t bf[2];
                bf[0] = f2tf(V[(kt * 8 + tig) * 68 + nt * 8 + gid]);
                bf[1] = f2tf(V[(kt * 8 + tig + 4) * 68 + nt * 8 + gid]);
                mma_tf32(o[0][nt], af[0], bf);
                mma_tf32(o[1][nt], af[1], bf);
            }
        }

        asm volatile("cp.async.wait_group 0;\n" ::: "memory");
        __syncthreads();
    }

    float lam = log1pf(__expf(lambda_p[h]));
    float inv[2][2] = {{1.f / l_[0][0], 1.f / l_[0][1]},
                       {1.f / l_[1][0], 1.f / l_[1][1]}};

    __syncthreads();
    if (side == 1) {
        float* sO2 = sP + hloc * 2176;
#pragma unroll
        for (int mt = 0; mt < 2; mt++)
#pragma unroll
            for (int nt = 0; nt < 8; nt++) {
                int r0 = mt * 16 + gid, r1 = r0 + 8, cc = nt * 8 + 2 * tig;
                sO2[r0 * 68 + cc]     = o[mt][nt][0] * inv[mt][0];
                sO2[r0 * 68 + cc + 1] = o[mt][nt][1] * inv[mt][0];
                sO2[r1 * 68 + cc]     = o[mt][nt][2] * inv[mt][1];
                sO2[r1 * 68 + cc + 1] = o[mt][nt][3] * inv[mt][1];
            }
    }
    __syncthreads();
    if (side == 0) {
        const float* sO2 = sP + hloc * 2176;
        float* dst = g_ctx + ((size_t)(b * N_ + ph * 32)) * 768 + h * 64;
#pragma unroll
        for (int mt = 0; mt < 2; mt++)
#pragma unroll
            for (int nt = 0; nt < 8; nt++) {
                int r0 = mt * 16 + gid, r1 = r0 + 8, cc = nt * 8 + 2 * tig;
                float2 v0, v1;
                v0.x = o[mt][nt][0] * inv[mt][0] - lam * sO2[r0 * 68 + cc];
                v0.y = o[mt][nt][1] * inv[mt][0] - lam * sO2[r0 * 68 + cc + 1];
                v1.x = o[mt][nt][2] * inv[mt][1] - lam * sO2[r1 * 68 + cc];
                v1.y = o[mt][nt][3] * inv[mt][1] - lam * sO2[r1 * 68 + cc + 1];
                *reinterpret_cast<float2*>(dst + (size_t)r0 * 768 + cc) = v0;
                *reinterpret_cast<float2*>(dst + (size_t)r1 * 768 + cc) = v1;
            }
    }
}

// ---------------------------------------------------------------------------
// Launch
// ---------------------------------------------------------------------------
extern "C" void kernel_launch(void* const* d_in, const int* in_sizes, int n_in,
                              void* d_out, int out_size)
{
    const float* x      = (const float*)d_in[0];
    const float* Wq     = (const float*)d_in[1];
    const float* Wk     = (const float*)d_in[2];
    const float* Wv1    = (const float*)d_in[3];
    const float* Wv2    = (const float*)d_in[4];
    const float* lam_p  = (const float*)d_in[5];
    const float* Wo     = (const float*)d_in[6];
    const float* bo     = (const float*)d_in[7];
    float* out = (float*)d_out;

    float *proj, *ctx;
    cudaGetSymbolAddress((void**)&proj, g_proj);
    cudaGetSymbolAddress((void**)&ctx,  g_ctx);

    cudaFuncSetAttribute(attn_tc, cudaFuncAttributeMaxDynamicSharedMemorySize,
                         ATT_SMEM_BYTES);

    // fused projections: one GEMM [4096 x 2560 x 768]
    gemm_tf32<<<dim3(PROJ_N / TBN, M_ROWS / TBM), 256>>>(
        x, Wq, Wk, Wv1, Wv2, nullptr, proj, M_ROWS, PROJ_N, DIM_);

    // RoPE + qk-norm over q+k (32 contiguous 64-vectors per row)
    {
        int vec = M_ROWS * 32;
        rope_norm<<<(vec * 32 + 255) / 256, 256>>>(proj, 32, PROJ_N, vec);
    }

    // tensor-core windowed differential attention
    attn_tc<<<B_ * KV_ * SIDE_, 192, ATT_SMEM_BYTES>>>(lam_p);

    // output projection + bias
    gemm_tf32<<<dim3(DIM_ / TBN, M_ROWS / TBM), 256>>>(
        ctx, Wo, Wo, Wo, Wo, bo, out, M_ROWS, DIM_, DIM_);
}

// round 5
// speedup vs baseline: 7.1341x; 1.2521x over previous
#include <cuda_runtime.h>
#include <math.h>
#include <stdint.h>

// Problem constants
#define B_    4
#define N_    1024
#define DIM_  768
#define H_    12
#define KV_   4
#define D_    64
#define SIDE_ 32
#define WIN_  8
#define REP_  (H_ / KV_)       // 3
#define M_ROWS (B_ * N_)       // 4096

// Fused projection layout: [row][2560] = q(0..1535) | k(1536..2047) | v1(2048..2303) | v2(2304..2559)
#define PROJ_N 2560
#define OFF_K  1536

// ---------------------------------------------------------------------------
// Scratch
// ---------------------------------------------------------------------------
__device__ float g_x   [M_ROWS * DIM_];      // tf32-rounded x
__device__ float g_wqkv[PROJ_N * DIM_];      // tf32-rounded Wq|Wk|Wv1|Wv2
__device__ float g_wo  [DIM_ * DIM_];        // tf32-rounded Wo
__device__ float g_proj[M_ROWS * PROJ_N];
__device__ float g_ctx [M_ROWS * DIM_];

// ---------------------------------------------------------------------------
// PTX helpers
// ---------------------------------------------------------------------------
__device__ __forceinline__ float to_tf32(float x) {
    asm("cvt.rna.tf32.f32 %0, %0;" : "+f"(x));
    return x;
}
__device__ __forceinline__ uint32_t f2tf(float x) {
    asm("cvt.rna.tf32.f32 %0, %0;" : "+f"(x));
    return __float_as_uint(x);
}
__device__ __forceinline__ void mma_tf32(float* c, const uint32_t* a, const uint32_t* b) {
    asm volatile(
        "mma.sync.aligned.m16n8k8.row.col.f32.tf32.tf32.f32 "
        "{%0,%1,%2,%3}, {%4,%5,%6,%7}, {%8,%9}, {%0,%1,%2,%3};\n"
        : "+f"(c[0]), "+f"(c[1]), "+f"(c[2]), "+f"(c[3])
        : "r"(a[0]), "r"(a[1]), "r"(a[2]), "r"(a[3]), "r"(b[0]), "r"(b[1]));
}
__device__ __forceinline__ void cpa16(float* dst, const float* src) {
    unsigned u = (unsigned)__cvta_generic_to_shared(dst);
    asm volatile("cp.async.cg.shared.global [%0], [%1], 16;\n" :: "r"(u), "l"(src));
}

// ---------------------------------------------------------------------------
// Prep: tf32-round x, concat+round weights. float4 per thread, region dispatch.
// Region sizes in float4 units:
//   x      786432
//   Wq     294912   -> g_wqkv + 0
//   Wk      98304   -> g_wqkv + 294912*4
//   Wv1     49152
//   Wv2     49152
//   Wo     147456   -> g_wo
// ---------------------------------------------------------------------------
#define PREP_TOTAL 1425408

__global__ __launch_bounds__(256)
void prep_tf32(const float* __restrict__ x,  const float* __restrict__ Wq,
               const float* __restrict__ Wk, const float* __restrict__ Wv1,
               const float* __restrict__ Wv2,const float* __restrict__ Wo)
{
    int idx = blockIdx.x * 256 + threadIdx.x;
    if (idx >= PREP_TOTAL) return;

    const float4* src;
    float4* dst;
    if (idx < 786432)        { src = (const float4*)x   + idx;           dst = (float4*)g_x    + idx; }
    else if (idx < 1081344)  { int i = idx - 786432;  src = (const float4*)Wq  + i; dst = (float4*)g_wqkv + i; }
    else if (idx < 1179648)  { int i = idx - 1081344; src = (const float4*)Wk  + i; dst = (float4*)g_wqkv + 294912 + i; }
    else if (idx < 1228800)  { int i = idx - 1179648; src = (const float4*)Wv1 + i; dst = (float4*)g_wqkv + 393216 + i; }
    else if (idx < 1277952)  { int i = idx - 1228800; src = (const float4*)Wv2 + i; dst = (float4*)g_wqkv + 442368 + i; }
    else                     { int i = idx - 1277952; src = (const float4*)Wo  + i; dst = (float4*)g_wo   + i; }

    float4 v = *src;
    v.x = to_tf32(v.x); v.y = to_tf32(v.y);
    v.z = to_tf32(v.z); v.w = to_tf32(v.w);
    *dst = v;
}

// ---------------------------------------------------------------------------
// TF32 tensor-core GEMM: C[M,N] = A[M,K] * W[N,K]^T (+bias).
// Inputs MUST be pre-rounded to tf32. 128x128 block tile, TBK=32,
// 256 threads (8 warps, 2x4), warp tile 64x32, cp.async double buffering.
// Dynamic smem: 2 stages x (128x36 A + 128x36 W) floats = 73728 B.
// ---------------------------------------------------------------------------
#define TBM 128
#define TBN 128
#define TBK 32
#define GPAD 36
#define GEMM_SMEM_BYTES (2 * 2 * TBM * GPAD * 4)   // 73728

__global__ __launch_bounds__(256, 2)
void gemm_tf32(const float* __restrict__ A, const float* __restrict__ W,
               const float* __restrict__ bias, float* __restrict__ C,
               int M, int N, int K)
{
    extern __shared__ float sm[];
    float* As = sm;                       // [2][128][36]
    float* Ws = sm + 2 * TBM * GPAD;      // [2][128][36]

    const int tid  = threadIdx.x;
    const int lane = tid & 31;
    const int warp = tid >> 5;
    const int wm   = (warp & 1) * 64;
    const int wn   = (warp >> 1) * 32;
    const int gid  = lane >> 2;
    const int tig  = lane & 3;

    const int m0 = blockIdx.y * TBM;
    const int n0 = blockIdx.x * TBN;

    const int lr = tid >> 3;              // used with +32*i: rows 0..127 per matrix
    const int lc = (tid & 7) * 4;

    auto load_stage = [&](int st, int k0) {
#pragma unroll
        for (int i = 0; i < 4; i++) {
            int r = lr + 32 * i;
            cpa16(As + (st * TBM + r) * GPAD + lc, A + (size_t)(m0 + r) * K + k0 + lc);
            cpa16(Ws + (st * TBN + r) * GPAD + lc, W + (size_t)(n0 + r) * K + k0 + lc);
        }
        asm volatile("cp.async.commit_group;\n" ::: "memory");
    };

    float acc[4][4][4];
#pragma unroll
    for (int i = 0; i < 4; i++)
#pragma unroll
        for (int j = 0; j < 4; j++)
#pragma unroll
            for (int l = 0; l < 4; l++) acc[i][j][l] = 0.f;

    const int nkt = K / TBK;
    load_stage(0, 0);

    for (int kt = 0; kt < nkt; kt++) {
        const int cur = kt & 1;
        if (kt + 1 < nkt) {
            load_stage(cur ^ 1, (kt + 1) * TBK);
            asm volatile("cp.async.wait_group 1;\n" ::: "memory");
        } else {
            asm volatile("cp.async.wait_group 0;\n" ::: "memory");
        }
        __syncthreads();

        const float* Ab = As + cur * TBM * GPAD;
        const float* Wb = Ws + cur * TBN * GPAD;

#pragma unroll
        for (int ks = 0; ks < 4; ks++) {
            const int kk = ks * 8;
            uint32_t bfr[4][2];
#pragma unroll
            for (int nt = 0; nt < 4; nt++) {
                int n = wn + nt * 8 + gid;
                bfr[nt][0] = __float_as_uint(Wb[n * GPAD + kk + tig]);
                bfr[nt][1] = __float_as_uint(Wb[n * GPAD + kk + tig + 4]);
            }
#pragma unroll
            for (int mt = 0; mt < 4; mt++) {
                int m = wm + mt * 16 + gid;
                uint32_t af[4];
                af[0] = __float_as_uint(Ab[m * GPAD + kk + tig]);
                af[1] = __float_as_uint(Ab[(m + 8) * GPAD + kk + tig]);
                af[2] = __float_as_uint(Ab[m * GPAD + kk + tig + 4]);
                af[3] = __float_as_uint(Ab[(m + 8) * GPAD + kk + tig + 4]);
#pragma unroll
                for (int nt = 0; nt < 4; nt++)
                    mma_tf32(acc[mt][nt], af, bfr[nt]);
            }
        }
        __syncthreads();
    }

#pragma unroll
    for (int mt = 0; mt < 4; mt++) {
        int m = m0 + wm + mt * 16 + gid;
#pragma unroll
        for (int nt = 0; nt < 4; nt++) {
            int n = n0 + wn + nt * 8 + 2 * tig;
            float b0 = bias ? bias[n] : 0.f;
            float b1 = bias ? bias[n + 1] : 0.f;
            float2 r0 = make_float2(acc[mt][nt][0] + b0, acc[mt][nt][1] + b1);
            float2 r1 = make_float2(acc[mt][nt][2] + b0, acc[mt][nt][3] + b1);
            *reinterpret_cast<float2*>(C + (size_t)m * N + n) = r0;
            *reinterpret_cast<float2*>(C + (size_t)(m + 8) * N + n) = r1;
        }
    }
}

// ---------------------------------------------------------------------------
// 2D RoPE + qk-norm (one warp per 64-vector). q+k contiguous 32 vecs/row.
// ---------------------------------------------------------------------------
__global__ __launch_bounds__(256)
void rope_norm(float* __restrict__ buf, int vpr, int stride, int total_vec)
{
    const int gw   = (blockIdx.x * blockDim.x + threadIdx.x) >> 5;
    const int lane = threadIdx.x & 31;
    if (gw >= total_vec) return;

    const int row = gw / vpr;
    const int vec = gw - row * vpr;
    const int n   = row & (N_ - 1);
    const float ph = (float)(n >> 5);
    const float pw = (float)(n & 31);

    float* p = buf + (size_t)row * stride + vec * 64;
    float x0 = p[lane];
    float x1 = p[lane + 32];

    float inv = exp2f((float)lane * -0.4152410118609203f);
    float t0 = ph * inv, t1 = pw * inv;
    float c0, s0, c1, s1;
    sincosf(t0, &s0, &c0);
    sincosf(t1, &s1, &c1);

    float px0 = __shfl_xor_sync(0xffffffffu, x0, 1);
    float px1 = __shfl_xor_sync(0xffffffffu, x1, 1);
    float r0 = (lane & 1) ? px0 : -px0;
    float r1 = (lane & 1) ? px1 : -px1;

    float o0 = x0 * c0 + r0 * s0;
    float o1 = x1 * c1 + r1 * s1;

    float ss = o0 * o0 + o1 * o1;
#pragma unroll
    for (int o = 16; o; o >>= 1) ss += __shfl_xor_sync(0xffffffffu, ss, o);
    float sc = 1.f / (sqrtf(ss) + 1e-6f);

    p[lane]      = o0 * sc;
    p[lane + 32] = o1 * sc;
}

// ---------------------------------------------------------------------------
// Tensor-core windowed differential flash attention (reads g_proj).
// Block = (b, kh, ph): 512 blocks, 6 warps. Warp = (side, head).
// ctx output is tf32-rounded (feeds the Wo GEMM directly).
// ---------------------------------------------------------------------------
#define ATT_SMEM_FLOATS (17408 + 6912)
#define ATT_SMEM_BYTES  (ATT_SMEM_FLOATS * 4)

__global__ __launch_bounds__(192)
void attn_tc(const float* __restrict__ lambda_p)
{
    extern __shared__ float sm[];
    float* sKV = sm;            // [2][4][32][68]
    float* sP  = sm + 17408;    // [6][32][36]

    const int tid  = threadIdx.x;
    const int lane = tid & 31;
    const int warp = tid >> 5;
    const int gid  = lane >> 2;
    const int tig  = lane & 3;

    const int blk = blockIdx.x;
    const int ph  = blk & 31;
    const int kh  = (blk >> 5) & 3;
    const int b   = blk >> 7;

    const int side = warp / 3;
    const int hloc = warp - side * 3;
    const int h    = kh * 3 + hloc;

    const int rlo = max(ph - WIN_, 0);
    const int rhi = min(ph + WIN_, SIDE_ - 1);
    const int nit = rhi - rlo + 1;

    auto load_stage = [&](int st, int r) {
#pragma unroll
        for (int i = 0; i < 11; i++) {
            int idx = tid + i * 192;
            if (idx < 2048) {
                int arr = idx >> 9;
                int key = (idx >> 4) & 31;
                int f4  = (idx & 15) * 4;
                const float* src = g_proj + (size_t)(b * N_ + r * 32 + key) * PROJ_N
                                 + OFF_K + arr * 256 + kh * 64 + f4;
                cpa16(sKV + ((size_t)(st * 4 + arr) * 32 + key) * 68 + f4, src);
            }
        }
        asm volatile("cp.async.commit_group;\n" ::: "memory");
    };

    load_stage(0, rlo);

    uint32_t qf[2][8][4];
    {
        const float* qb = g_proj + ((size_t)(b * N_ + ph * 32)) * PROJ_N + side * 768 + h * 64;
#pragma unroll
        for (int mt = 0; mt < 2; mt++) {
            const float* q0 = qb + (size_t)(mt * 16 + gid) * PROJ_N;
            const float* q1 = q0 + (size_t)8 * PROJ_N;
#pragma unroll
            for (int kt = 0; kt < 8; kt++) {
                qf[mt][kt][0] = f2tf(q0[kt * 8 + tig]);
                qf[mt][kt][1] = f2tf(q1[kt * 8 + tig]);
                qf[mt][kt][2] = f2tf(q0[kt * 8 + tig + 4]);
                qf[mt][kt][3] = f2tf(q1[kt * 8 + tig + 4]);
            }
        }
    }

    float o[2][8][4];
#pragma unroll
    for (int mt = 0; mt < 2; mt++)
#pragma unroll
        for (int nt = 0; nt < 8; nt++)
#pragma unroll
            for (int c = 0; c < 4; c++) o[mt][nt][c] = 0.f;

    float m_[2][2] = {{-1e30f, -1e30f}, {-1e30f, -1e30f}};
    float l_[2][2] = {{0.f, 0.f}, {0.f, 0.f}};

    float* sPw = sP + warp * 1152;

    asm volatile("cp.async.wait_group 0;\n" ::: "memory");
    __syncthreads();

    for (int it = 0; it < nit; it++) {
        const int cur = it & 1;
        if (it + 1 < nit) load_stage(cur ^ 1, rlo + it + 1);

        const float* K = sKV + (size_t)(cur * 4 + side) * 32 * 68;
        const float* V = sKV + (size_t)(cur * 4 + 2 + side) * 32 * 68;

        float s[2][4][4];
#pragma unroll
        for (int mt = 0; mt < 2; mt++)
#pragma unroll
            for (int nt = 0; nt < 4; nt++)
#pragma unroll
                for (int c = 0; c < 4; c++) s[mt][nt][c] = 0.f;

#pragma unroll
        for (int kt = 0; kt < 8; kt++) {
            uint32_t bf[4][2];
#pragma unroll
            for (int nt = 0; nt < 4; nt++) {
                bf[nt][0] = f2tf(K[(nt * 8 + gid) * 68 + kt * 8 + tig]);
                bf[nt][1] = f2tf(K[(nt * 8 + gid) * 68 + kt * 8 + tig + 4]);
            }
#pragma unroll
            for (int mt = 0; mt < 2; mt++)
#pragma unroll
                for (int nt = 0; nt < 4; nt++)
                    mma_tf32(s[mt][nt], qf[mt][kt], bf[nt]);
        }

        float mnew[2][2] = {{m_[0][0], m_[0][1]}, {m_[1][0], m_[1][1]}};
#pragma unroll
        for (int mt = 0; mt < 2; mt++)
#pragma unroll
            for (int nt = 0; nt < 4; nt++)
#pragma unroll
                for (int c = 0; c < 4; c++) {
                    int half = c >> 1;
                    int pw = mt * 16 + gid + half * 8;
                    int ck = nt * 8 + 2 * tig + (c & 1);
                    float v = s[mt][nt][c] * 0.125f;
                    int d = pw - ck; d = (d < 0) ? -d : d;
                    v = (d > WIN_) ? -1e30f : v;
                    s[mt][nt][c] = v;
                    mnew[mt][half] = fmaxf(mnew[mt][half], v);
                }
#pragma unroll
        for (int mt = 0; mt < 2; mt++)
#pragma unroll
            for (int hf = 0; hf < 2; hf++) {
                float mm = mnew[mt][hf];
                mm = fmaxf(mm, __shfl_xor_sync(0xffffffffu, mm, 1));
                mm = fmaxf(mm, __shfl_xor_sync(0xffffffffu, mm, 2));
                mnew[mt][hf] = mm;
            }

        float scl[2][2];
#pragma unroll
        for (int mt = 0; mt < 2; mt++)
#pragma unroll
            for (int hf = 0; hf < 2; hf++) {
                scl[mt][hf] = __expf(m_[mt][hf] - mnew[mt][hf]);
                m_[mt][hf] = mnew[mt][hf];
            }

        __syncwarp();
        float rs[2][2] = {{0.f, 0.f}, {0.f, 0.f}};
#pragma unroll
        for (int mt = 0; mt < 2; mt++)
#pragma unroll
            for (int nt = 0; nt < 4; nt++) {
                float p0 = __expf(s[mt][nt][0] - m_[mt][0]);
                float p1 = __expf(s[mt][nt][1] - m_[mt][0]);
                float p2 = __expf(s[mt][nt][2] - m_[mt][1]);
                float p3 = __expf(s[mt][nt][3] - m_[mt][1]);
                rs[mt][0] += p0 + p1;
                rs[mt][1] += p2 + p3;
                int r0 = mt * 16 + gid, r1 = r0 + 8, cc = nt * 8 + 2 * tig;
                sPw[r0 * 36 + cc]     = __uint_as_float(f2tf(p0));
                sPw[r0 * 36 + cc + 1] = __uint_as_float(f2tf(p1));
                sPw[r1 * 36 + cc]     = __uint_as_float(f2tf(p2));
                sPw[r1 * 36 + cc + 1] = __uint_as_float(f2tf(p3));
            }
#pragma unroll
        for (int mt = 0; mt < 2; mt++)
#pragma unroll
            for (int hf = 0; hf < 2; hf++) {
                float r = rs[mt][hf];
                r += __shfl_xor_sync(0xffffffffu, r, 1);
                r += __shfl_xor_sync(0xffffffffu, r, 2);
                l_[mt][hf] = l_[mt][hf] * scl[mt][hf] + r;
            }
#pragma unroll
        for (int mt = 0; mt < 2; mt++)
#pragma unroll
            for (int nt = 0; nt < 8; nt++) {
                o[mt][nt][0] *= scl[mt][0];
                o[mt][nt][1] *= scl[mt][0];
                o[mt][nt][2] *= scl[mt][1];
                o[mt][nt][3] *= scl[mt][1];
            }

        __syncwarp();

#pragma unroll
        for (int kt = 0; kt < 4; kt++) {
            uint32_t af[2][4];
#pragma unroll
            for (int mt = 0; mt < 2; mt++) {
                int r0 = mt * 16 + gid;
                af[mt][0] = __float_as_uint(sPw[r0 * 36 + kt * 8 + tig]);
                af[mt][1] = __float_as_uint(sPw[(r0 + 8) * 36 + kt * 8 + tig]);
                af[mt][2] = __float_as_uint(sPw[r0 * 36 + kt * 8 + tig + 4]);
                af[mt][3] = __float_as_uint(sPw[(r0 + 8) * 36 + kt * 8 + tig + 4]);
            }
#pragma unroll
            for (int nt = 0; nt < 8; nt++) {
                uint32_t bf[2];
                bf[0] = f2tf(V[(kt * 8 + tig) * 68 + nt * 8 + gid]);
                bf[1] = f2tf(V[(kt * 8 + tig + 4) * 68 + nt * 8 + gid]);
                mma_tf32(o[0][nt], af[0], bf);
                mma_tf32(o[1][nt], af[1], bf);
            }
        }

        asm volatile("cp.async.wait_group 0;\n" ::: "memory");
        __syncthreads();
    }

    float lam = log1pf(__expf(lambda_p[h]));
    float inv[2][2] = {{1.f / l_[0][0], 1.f / l_[0][1]},
                       {1.f / l_[1][0], 1.f / l_[1][1]}};

    __syncthreads();
    if (side == 1) {
        float* sO2 = sP + hloc * 2176;
#pragma unroll
        for (int mt = 0; mt < 2; mt++)
#pragma unroll
            for (int nt = 0; nt < 8; nt++) {
                int r0 = mt * 16 + gid, r1 = r0 + 8, cc = nt * 8 + 2 * tig;
                sO2[r0 * 68 + cc]     = o[mt][nt][0] * inv[mt][0];
                sO2[r0 * 68 + cc + 1] = o[mt][nt][1] * inv[mt][0];
                sO2[r1 * 68 + cc]     = o[mt][nt][2] * inv[mt][1];
                sO2[r1 * 68 + cc + 1] = o[mt][nt][3] * inv[mt][1];
            }
    }
    __syncthreads();
    if (side == 0) {
        const float* sO2 = sP + hloc * 2176;
        float* dst = g_ctx + ((size_t)(b * N_ + ph * 32)) * 768 + h * 64;
#pragma unroll
        for (int mt = 0; mt < 2; mt++)
#pragma unroll
            for (int nt = 0; nt < 8; nt++) {
                int r0 = mt * 16 + gid, r1 = r0 + 8, cc = nt * 8 + 2 * tig;
                float2 v0, v1;
                v0.x = to_tf32(o[mt][nt][0] * inv[mt][0] - lam * sO2[r0 * 68 + cc]);
                v0.y = to_tf32(o[mt][nt][1] * inv[mt][0] - lam * sO2[r0 * 68 + cc + 1]);
                v1.x = to_tf32(o[mt][nt][2] * inv[mt][1] - lam * sO2[r1 * 68 + cc]);
                v1.y = to_tf32(o[mt][nt][3] * inv[mt][1] - lam * sO2[r1 * 68 + cc + 1]);
                *reinterpret_cast<float2*>(dst + (size_t)r0 * 768 + cc) = v0;
                *reinterpret_cast<float2*>(dst + (size_t)r1 * 768 + cc) = v1;
            }
    }
}

// ---------------------------------------------------------------------------
// Launch
// ---------------------------------------------------------------------------
extern "C" void kernel_launch(void* const* d_in, const int* in_sizes, int n_in,
                              void* d_out, int out_size)
{
    const float* x      = (const float*)d_in[0];
    const float* Wq     = (const float*)d_in[1];
    const float* Wk     = (const float*)d_in[2];
    const float* Wv1    = (const float*)d_in[3];
    const float* Wv2    = (const float*)d_in[4];
    const float* lam_p  = (const float*)d_in[5];
    const float* Wo     = (const float*)d_in[6];
    const float* bo     = (const float*)d_in[7];
    float* out = (float*)d_out;

    float *gx, *gw, *gwo, *proj, *ctx;
    cudaGetSymbolAddress((void**)&gx,   g_x);
    cudaGetSymbolAddress((void**)&gw,   g_wqkv);
    cudaGetSymbolAddress((void**)&gwo,  g_wo);
    cudaGetSymbolAddress((void**)&proj, g_proj);
    cudaGetSymbolAddress((void**)&ctx,  g_ctx);

    cudaFuncSetAttribute(gemm_tf32, cudaFuncAttributeMaxDynamicSharedMemorySize,
                         GEMM_SMEM_BYTES);
    cudaFuncSetAttribute(attn_tc, cudaFuncAttributeMaxDynamicSharedMemorySize,
                         ATT_SMEM_BYTES);

    // tf32 pre-rounding + weight concat
    prep_tf32<<<(PREP_TOTAL + 255) / 256, 256>>>(x, Wq, Wk, Wv1, Wv2, Wo);

    // fused projections: one GEMM [4096 x 2560 x 768]
    gemm_tf32<<<dim3(PROJ_N / TBN, M_ROWS / TBM), 256, GEMM_SMEM_BYTES>>>(
        gx, gw, nullptr, proj, M_ROWS, PROJ_N, DIM_);

    // RoPE + qk-norm over q+k (32 contiguous 64-vectors per row)
    {
        int vec = M_ROWS * 32;
        rope_norm<<<(vec * 32 + 255) / 256, 256>>>(proj, 32, PROJ_N, vec);
    }

    // tensor-core windowed differential attention
    attn_tc<<<B_ * KV_ * SIDE_, 192, ATT_SMEM_BYTES>>>(lam_p);

    // output projection + bias
    gemm_tf32<<<dim3(DIM_ / TBN, M_ROWS / TBM), 256, GEMM_SMEM_BYTES>>>(
        ctx, gwo, bo, out, M_ROWS, DIM_, DIM_);
}